// round 1
// baseline (speedup 1.0000x reference)
#include <cuda_runtime.h>
#include <cuda_bf16.h>
#include <cstdint>

// Problem constants (fixed by the reference)
#define N_NODES 100000
#define N_EDGES 1600000
#define D_IN    128
#define D_OUT   128

// Scratch: h = x @ W^T + b  (51.2 MB) and transposed weights (64 KB)
__device__ float g_h[(size_t)N_NODES * D_OUT];
__device__ float g_Wt[D_IN * D_OUT];  // g_Wt[d * D_OUT + o] = W[o * D_IN + d]

// ---------------------------------------------------------------------------
// Kernel 1: transpose W [D_OUT, D_IN] -> Wt [D_IN, D_OUT]  (tiny, 16K elems)
// ---------------------------------------------------------------------------
__global__ void k_transpose_w(const float* __restrict__ W) {
    int idx = blockIdx.x * blockDim.x + threadIdx.x;   // 0..16383
    if (idx >= D_OUT * D_IN) return;
    int o = idx >> 7;          // row of W
    int d = idx & 127;         // col of W
    g_Wt[d * D_OUT + o] = W[o * D_IN + d];
}

// ---------------------------------------------------------------------------
// Kernel 2: h[n][o] = sum_d x[n][d] * W[o][d] + b[o]
// Block = 256 threads = 8 warps = 8 nodes. Each lane owns 4 output columns.
// Per d: broadcast x from smem, contiguous float4 read of Wt row (L1/L2 hot).
// ---------------------------------------------------------------------------
__global__ void k_gemm(const float* __restrict__ x, const float* __restrict__ b) {
    __shared__ float xs[8][D_IN];

    const int tid   = threadIdx.x;
    const int node0 = blockIdx.x * 8;

    // Cooperative load of 8 x-rows (1024 floats = 256 float4, perfectly coalesced)
    {
        const float4* src = reinterpret_cast<const float4*>(x + (size_t)node0 * D_IN);
        reinterpret_cast<float4*>(&xs[0][0])[tid] = src[tid];
    }
    __syncthreads();

    const int w = tid >> 5;          // warp -> node within block
    const int l = tid & 31;          // lane -> column quad

    const float*  xr  = xs[w];
    const float4* Wt4 = reinterpret_cast<const float4*>(g_Wt);   // row d: Wt4[d*32 + l]

    float4 acc = reinterpret_cast<const float4*>(b)[l];          // init with bias

#pragma unroll 8
    for (int d = 0; d < D_IN; d++) {
        const float  xv = xr[d];
        const float4 wv = Wt4[d * 32 + l];
        acc.x = fmaf(xv, wv.x, acc.x);
        acc.y = fmaf(xv, wv.y, acc.y);
        acc.z = fmaf(xv, wv.z, acc.z);
        acc.w = fmaf(xv, wv.w, acc.w);
    }

    reinterpret_cast<float4*>(g_h + (size_t)(node0 + w) * D_OUT)[l] = acc;
}

// ---------------------------------------------------------------------------
// Kernel 3: zero the output (it is poisoned by the harness)
// ---------------------------------------------------------------------------
__global__ void k_zero(float4* __restrict__ out, int n4) {
    int i = blockIdx.x * blockDim.x + threadIdx.x;
    if (i < n4) out[i] = make_float4(0.f, 0.f, 0.f, 0.f);
}

// ---------------------------------------------------------------------------
// Kernel 4: scatter-add.  One warp per edge.
//   lane: float4 of h[src] * w  ->  red.global.add.v4.f32 into out[dst]
// ---------------------------------------------------------------------------
__global__ void k_scatter(const float* __restrict__ ew,
                          const int*   __restrict__ src,
                          const int*   __restrict__ dst,
                          float*       __restrict__ out) {
    const int warp = (blockIdx.x * blockDim.x + threadIdx.x) >> 5;
    if (warp >= N_EDGES) return;
    const int l = threadIdx.x & 31;

    const int   s = src[warp];
    const int   t = dst[warp];
    const float wgt = ew[warp];

    const float4 hv = reinterpret_cast<const float4*>(g_h + (size_t)s * D_OUT)[l];

    float* p = out + (size_t)t * D_OUT + l * 4;
    asm volatile("red.global.add.v4.f32 [%0], {%1, %2, %3, %4};"
                 :: "l"(p),
                    "f"(wgt * hv.x), "f"(wgt * hv.y),
                    "f"(wgt * hv.z), "f"(wgt * hv.w)
                 : "memory");
}

// ---------------------------------------------------------------------------
// Kernel 5: in-place ReLU on output
// ---------------------------------------------------------------------------
__global__ void k_relu(float4* __restrict__ out, int n4) {
    int i = blockIdx.x * blockDim.x + threadIdx.x;
    if (i < n4) {
        float4 v = out[i];
        v.x = fmaxf(v.x, 0.f);
        v.y = fmaxf(v.y, 0.f);
        v.z = fmaxf(v.z, 0.f);
        v.w = fmaxf(v.w, 0.f);
        out[i] = v;
    }
}

// ---------------------------------------------------------------------------
// Launch.  Inputs (metadata order): x, W, b, edge_weight, edge_src, edge_dst
// ---------------------------------------------------------------------------
extern "C" void kernel_launch(void* const* d_in, const int* in_sizes, int n_in,
                              void* d_out, int out_size) {
    const float* x  = (const float*)d_in[0];
    const float* W  = (const float*)d_in[1];
    const float* b  = (const float*)d_in[2];
    const float* ew = (const float*)d_in[3];
    const int*   es = (const int*)  d_in[4];
    const int*   ed = (const int*)  d_in[5];
    float*       out = (float*)d_out;

    // 1) transpose W (tiny)
    k_transpose_w<<<(D_IN * D_OUT + 255) / 256, 256>>>(W);

    // 2) GEMM: 100000 nodes / 8 per block
    k_gemm<<<N_NODES / 8, 256>>>(x, b);

    // 3) zero output: 12.8M floats -> 3.2M float4
    const int n4 = (N_NODES * D_OUT) / 4;
    k_zero<<<(n4 + 255) / 256, 256>>>((float4*)out, n4);

    // 4) scatter: 1 warp/edge, 8 edges per 256-thread block
    k_scatter<<<(N_EDGES + 7) / 8, 256>>>(ew, es, ed, out);

    // 5) ReLU
    k_relu<<<(n4 + 255) / 256, 256>>>((float4*)out, n4);
}

// round 3
// speedup vs baseline: 1.3326x; 1.3326x over previous
#include <cuda_runtime.h>
#include <cuda_bf16.h>
#include <cstdint>

// Problem constants (fixed by the reference)
#define N_NODES 100000
#define N_EDGES 1600000
#define D_IN    128
#define D_OUT   128

#define SCAN_BLK 1024
#define N_SCAN_BLOCKS ((N_NODES + SCAN_BLK - 1) / SCAN_BLK)   // 98

// Scratch (all static __device__ — no allocation)
__device__ float g_h[(size_t)N_NODES * D_OUT];   // 51.2 MB, fits in L2
__device__ float g_Wt[D_IN * D_OUT];             // W transposed
__device__ int   g_deg[N_NODES];                 // degree -> exclusive scan (in place)
__device__ int   g_rowstart[N_NODES + 1];
__device__ int   g_cursor[N_NODES];
__device__ int   g_blocksums[N_SCAN_BLOCKS];
__device__ int   g_blockoff[N_SCAN_BLOCKS];
__device__ int   g_csr_src[N_EDGES];             // packed by dst
__device__ float g_csr_w[N_EDGES];

// ---------------------------------------------------------------------------
// 1: transpose W [D_OUT, D_IN] -> Wt [D_IN, D_OUT]
// ---------------------------------------------------------------------------
__global__ void k_transpose_w(const float* __restrict__ W) {
    int idx = blockIdx.x * blockDim.x + threadIdx.x;
    if (idx >= D_OUT * D_IN) return;
    int o = idx >> 7;
    int d = idx & 127;
    g_Wt[d * D_OUT + o] = W[o * D_IN + d];
}

// ---------------------------------------------------------------------------
// 2: h[n][o] = sum_d x[n][d] * W[o][d] + b[o]   (warp per node, lane = 4 cols)
// ---------------------------------------------------------------------------
__global__ void k_gemm(const float* __restrict__ x, const float* __restrict__ b) {
    __shared__ float xs[8][D_IN];

    const int tid   = threadIdx.x;
    const int node0 = blockIdx.x * 8;

    {
        const float4* src = reinterpret_cast<const float4*>(x + (size_t)node0 * D_IN);
        reinterpret_cast<float4*>(&xs[0][0])[tid] = src[tid];
    }
    __syncthreads();

    const int w = tid >> 5;
    const int l = tid & 31;

    const float*  xr  = xs[w];
    const float4* Wt4 = reinterpret_cast<const float4*>(g_Wt);

    float4 acc = reinterpret_cast<const float4*>(b)[l];

#pragma unroll 8
    for (int d = 0; d < D_IN; d++) {
        const float  xv = xr[d];
        const float4 wv = Wt4[d * 32 + l];
        acc.x = fmaf(xv, wv.x, acc.x);
        acc.y = fmaf(xv, wv.y, acc.y);
        acc.z = fmaf(xv, wv.z, acc.z);
        acc.w = fmaf(xv, wv.w, acc.w);
    }

    reinterpret_cast<float4*>(g_h + (size_t)(node0 + w) * D_OUT)[l] = acc;
}

// ---------------------------------------------------------------------------
// CSR build: zero degrees -> histogram -> scan (3 kernels) -> fill
// ---------------------------------------------------------------------------
__global__ void k_zero_deg() {
    int i = blockIdx.x * blockDim.x + threadIdx.x;
    if (i < N_NODES) g_deg[i] = 0;
}

__global__ void k_hist(const int* __restrict__ dst) {
    int e = blockIdx.x * blockDim.x + threadIdx.x;
    if (e < N_EDGES) atomicAdd(&g_deg[dst[e]], 1);
}

// block-level exclusive scan (in place on g_deg), block sums out
__global__ void k_scan1() {
    __shared__ int sh[2][SCAN_BLK];
    const int tid = threadIdx.x;
    const int gid = blockIdx.x * SCAN_BLK + tid;

    int v = (gid < N_NODES) ? g_deg[gid] : 0;
    sh[0][tid] = v;
    __syncthreads();

    int cur = 0;
    for (int off = 1; off < SCAN_BLK; off <<= 1) {
        int t = sh[cur][tid];
        if (tid >= off) t += sh[cur][tid - off];
        sh[cur ^ 1][tid] = t;
        cur ^= 1;
        __syncthreads();
    }
    // exclusive = inclusive - v
    if (gid < N_NODES) g_deg[gid] = sh[cur][tid] - v;
    if (tid == SCAN_BLK - 1) g_blocksums[blockIdx.x] = sh[cur][tid];
}

__global__ void k_scan2() {
    if (threadIdx.x == 0) {
        int acc = 0;
        for (int i = 0; i < N_SCAN_BLOCKS; i++) {
            g_blockoff[i] = acc;
            acc += g_blocksums[i];
        }
    }
}

__global__ void k_scan3() {
    int gid = blockIdx.x * blockDim.x + threadIdx.x;
    if (gid < N_NODES) {
        int rs = g_deg[gid] + g_blockoff[gid / SCAN_BLK];
        g_rowstart[gid] = rs;
        g_cursor[gid]   = rs;
    }
    if (gid == 0) g_rowstart[N_NODES] = N_EDGES;
}

__global__ void k_fill(const int*   __restrict__ src,
                       const int*   __restrict__ dst,
                       const float* __restrict__ ew) {
    int e = blockIdx.x * blockDim.x + threadIdx.x;
    if (e >= N_EDGES) return;
    int d   = dst[e];
    int pos = atomicAdd(&g_cursor[d], 1);
    g_csr_src[pos] = src[e];
    g_csr_w[pos]   = ew[e];
}

// ---------------------------------------------------------------------------
// Gather: warp per dst node. acc += w_e * h[src_e][lane*4..+3]; fused ReLU.
// h is L2-resident (51.2 MB < 126 MB L2) -> gather runs at LTS throughput.
// 4-deep software pipeline to keep >=4 independent loads in flight per warp.
// ---------------------------------------------------------------------------
__global__ void k_gather(float* __restrict__ out) {
    const int node = (blockIdx.x * blockDim.x + threadIdx.x) >> 5;
    if (node >= N_NODES) return;
    const int l = threadIdx.x & 31;

    const int beg = g_rowstart[node];
    const int end = g_rowstart[node + 1];

    const float4* h4 = reinterpret_cast<const float4*>(g_h);
    float4 acc = make_float4(0.f, 0.f, 0.f, 0.f);

    int e = beg;
    for (; e + 3 < end; e += 4) {
        const int   s0 = g_csr_src[e];
        const int   s1 = g_csr_src[e + 1];
        const int   s2 = g_csr_src[e + 2];
        const int   s3 = g_csr_src[e + 3];
        const float w0 = g_csr_w[e];
        const float w1 = g_csr_w[e + 1];
        const float w2 = g_csr_w[e + 2];
        const float w3 = g_csr_w[e + 3];
        const float4 h0 = h4[(size_t)s0 * 32 + l];
        const float4 h1 = h4[(size_t)s1 * 32 + l];
        const float4 h2 = h4[(size_t)s2 * 32 + l];
        const float4 h3 = h4[(size_t)s3 * 32 + l];
        acc.x = fmaf(w0, h0.x, acc.x); acc.y = fmaf(w0, h0.y, acc.y);
        acc.z = fmaf(w0, h0.z, acc.z); acc.w = fmaf(w0, h0.w, acc.w);
        acc.x = fmaf(w1, h1.x, acc.x); acc.y = fmaf(w1, h1.y, acc.y);
        acc.z = fmaf(w1, h1.z, acc.z); acc.w = fmaf(w1, h1.w, acc.w);
        acc.x = fmaf(w2, h2.x, acc.x); acc.y = fmaf(w2, h2.y, acc.y);
        acc.z = fmaf(w2, h2.z, acc.z); acc.w = fmaf(w2, h2.w, acc.w);
        acc.x = fmaf(w3, h3.x, acc.x); acc.y = fmaf(w3, h3.y, acc.y);
        acc.z = fmaf(w3, h3.z, acc.z); acc.w = fmaf(w3, h3.w, acc.w);
    }
    for (; e < end; e++) {
        const int   s0 = g_csr_src[e];
        const float w0 = g_csr_w[e];
        const float4 h0 = h4[(size_t)s0 * 32 + l];
        acc.x = fmaf(w0, h0.x, acc.x); acc.y = fmaf(w0, h0.y, acc.y);
        acc.z = fmaf(w0, h0.z, acc.z); acc.w = fmaf(w0, h0.w, acc.w);
    }

    acc.x = fmaxf(acc.x, 0.f);
    acc.y = fmaxf(acc.y, 0.f);
    acc.z = fmaxf(acc.z, 0.f);
    acc.w = fmaxf(acc.w, 0.f);

    reinterpret_cast<float4*>(out)[(size_t)node * 32 + l] = acc;
}

// ---------------------------------------------------------------------------
// Launch.  Inputs: x, W, b, edge_weight, edge_src, edge_dst
// ---------------------------------------------------------------------------
extern "C" void kernel_launch(void* const* d_in, const int* in_sizes, int n_in,
                              void* d_out, int out_size) {
    const float* x  = (const float*)d_in[0];
    const float* W  = (const float*)d_in[1];
    const float* b  = (const float*)d_in[2];
    const float* ew = (const float*)d_in[3];
    const int*   es = (const int*)  d_in[4];
    const int*   ed = (const int*)  d_in[5];
    float*       out = (float*)d_out;

    // Linear layer
    k_transpose_w<<<(D_IN * D_OUT + 255) / 256, 256>>>(W);
    k_gemm<<<N_NODES / 8, 256>>>(x, b);

    // CSR-by-dst build
    k_zero_deg<<<(N_NODES + 255) / 256, 256>>>();
    k_hist<<<(N_EDGES + 255) / 256, 256>>>(ed);
    k_scan1<<<N_SCAN_BLOCKS, SCAN_BLK>>>();
    k_scan2<<<1, 32>>>();
    k_scan3<<<(N_NODES + 255) / 256, 256>>>();
    k_fill<<<(N_EDGES + 255) / 256, 256>>>(es, ed, ew);

    // Gather + fused ReLU (writes every output exactly once)
    k_gather<<<(N_NODES * 32 + 255) / 256, 256>>>(out);
}

// round 4
// speedup vs baseline: 2.0252x; 1.5198x over previous
#include <cuda_runtime.h>
#include <cuda_bf16.h>
#include <cstdint>

// Problem constants (fixed by the reference)
#define N_NODES 100000
#define N_EDGES 1600000
#define D_IN    128
#define D_OUT   128

#define SCAN_BLK 1024
#define N_SCAN_BLOCKS ((N_NODES + SCAN_BLK - 1) / SCAN_BLK)   // 98

// Scratch (all static __device__ — no allocation)
__device__ float g_h[(size_t)N_NODES * D_OUT];   // 51.2 MB, fits in L2
__device__ float g_Wt[D_IN * D_OUT];             // W transposed
__device__ int   g_deg[N_NODES];                 // degree -> exclusive scan (in place)
__device__ int   g_rowstart[N_NODES + 1];
__device__ int   g_cursor[N_NODES];
__device__ int   g_blocksums[N_SCAN_BLOCKS];
__device__ int   g_blockoff[N_SCAN_BLOCKS];
__device__ int   g_csr_src[N_EDGES];             // packed by dst
__device__ float g_csr_w[N_EDGES];

// ---------------------------------------------------------------------------
// 1: transpose W [D_OUT, D_IN] -> Wt [D_IN, D_OUT]
// ---------------------------------------------------------------------------
__global__ void k_transpose_w(const float* __restrict__ W) {
    int idx = blockIdx.x * blockDim.x + threadIdx.x;
    if (idx >= D_OUT * D_IN) return;
    int o = idx >> 7;
    int d = idx & 127;
    g_Wt[d * D_OUT + o] = W[o * D_IN + d];
}

// ---------------------------------------------------------------------------
// 2: h[n][o] = x[n]·W[o] + b[o]
// Register-blocked: block = 256 thr = 8 warps, 32 nodes/block, 4 nodes/warp.
// Per d: ONE 512B Wt row load per warp serves 16 FFMAs -> L1 traffic /4,
// kernel becomes FFMA-issue-bound (~91us floor) instead of L1-bound (~182us).
// ---------------------------------------------------------------------------
__global__ void k_gemm(const float* __restrict__ x, const float* __restrict__ b) {
    __shared__ float xs[32][D_IN];   // 16 KB

    const int tid   = threadIdx.x;
    const int node0 = blockIdx.x * 32;

    // Cooperative load of 32 x-rows: 1024 float4, 4 per thread, coalesced
    {
        const float4* src  = reinterpret_cast<const float4*>(x + (size_t)node0 * D_IN);
        float4*       dst4 = reinterpret_cast<float4*>(&xs[0][0]);
#pragma unroll
        for (int k = 0; k < 4; k++)
            dst4[tid + k * 256] = src[tid + k * 256];
    }
    __syncthreads();

    const int w  = tid >> 5;      // warp id -> node quad
    const int l  = tid & 31;      // lane -> 4 output columns
    const int n0 = w * 4;

    const float4* Wt4  = reinterpret_cast<const float4*>(g_Wt);
    const float4  bias = reinterpret_cast<const float4*>(b)[l];

    float4 a0 = bias, a1 = bias, a2 = bias, a3 = bias;

#pragma unroll 4
    for (int d = 0; d < D_IN; d++) {
        const float4 wv = Wt4[d * 32 + l];          // one L1 load, 4-node reuse
        const float  x0 = xs[n0 + 0][d];            // broadcast LDS, no conflicts
        const float  x1 = xs[n0 + 1][d];
        const float  x2 = xs[n0 + 2][d];
        const float  x3 = xs[n0 + 3][d];
        a0.x = fmaf(x0, wv.x, a0.x); a0.y = fmaf(x0, wv.y, a0.y);
        a0.z = fmaf(x0, wv.z, a0.z); a0.w = fmaf(x0, wv.w, a0.w);
        a1.x = fmaf(x1, wv.x, a1.x); a1.y = fmaf(x1, wv.y, a1.y);
        a1.z = fmaf(x1, wv.z, a1.z); a1.w = fmaf(x1, wv.w, a1.w);
        a2.x = fmaf(x2, wv.x, a2.x); a2.y = fmaf(x2, wv.y, a2.y);
        a2.z = fmaf(x2, wv.z, a2.z); a2.w = fmaf(x2, wv.w, a2.w);
        a3.x = fmaf(x3, wv.x, a3.x); a3.y = fmaf(x3, wv.y, a3.y);
        a3.z = fmaf(x3, wv.z, a3.z); a3.w = fmaf(x3, wv.w, a3.w);
    }

    float4* hout = reinterpret_cast<float4*>(g_h);
    const size_t base = (size_t)(node0 + n0) * 32 + l;
    hout[base]      = a0;
    hout[base + 32] = a1;
    hout[base + 64] = a2;
    hout[base + 96] = a3;
}

// ---------------------------------------------------------------------------
// CSR build: zero degrees -> histogram -> scan (3 kernels) -> fill
// ---------------------------------------------------------------------------
__global__ void k_zero_deg() {
    int i = blockIdx.x * blockDim.x + threadIdx.x;
    if (i < N_NODES) g_deg[i] = 0;
}

__global__ void k_hist(const int* __restrict__ dst) {
    int e = blockIdx.x * blockDim.x + threadIdx.x;
    if (e < N_EDGES) atomicAdd(&g_deg[dst[e]], 1);
}

// block-level exclusive scan (in place on g_deg), block sums out
__global__ void k_scan1() {
    __shared__ int sh[2][SCAN_BLK];
    const int tid = threadIdx.x;
    const int gid = blockIdx.x * SCAN_BLK + tid;

    int v = (gid < N_NODES) ? g_deg[gid] : 0;
    sh[0][tid] = v;
    __syncthreads();

    int cur = 0;
    for (int off = 1; off < SCAN_BLK; off <<= 1) {
        int t = sh[cur][tid];
        if (tid >= off) t += sh[cur][tid - off];
        sh[cur ^ 1][tid] = t;
        cur ^= 1;
        __syncthreads();
    }
    if (gid < N_NODES) g_deg[gid] = sh[cur][tid] - v;   // exclusive
    if (tid == SCAN_BLK - 1) g_blocksums[blockIdx.x] = sh[cur][tid];
}

__global__ void k_scan2() {
    if (threadIdx.x == 0) {
        int acc = 0;
        for (int i = 0; i < N_SCAN_BLOCKS; i++) {
            g_blockoff[i] = acc;
            acc += g_blocksums[i];
        }
    }
}

__global__ void k_scan3() {
    int gid = blockIdx.x * blockDim.x + threadIdx.x;
    if (gid < N_NODES) {
        int rs = g_deg[gid] + g_blockoff[gid / SCAN_BLK];
        g_rowstart[gid] = rs;
        g_cursor[gid]   = rs;
    }
    if (gid == 0) g_rowstart[N_NODES] = N_EDGES;
}

__global__ void k_fill(const int*   __restrict__ src,
                       const int*   __restrict__ dst,
                       const float* __restrict__ ew) {
    int e = blockIdx.x * blockDim.x + threadIdx.x;
    if (e >= N_EDGES) return;
    int d   = dst[e];
    int pos = atomicAdd(&g_cursor[d], 1);
    g_csr_src[pos] = src[e];
    g_csr_w[pos]   = ew[e];
}

// ---------------------------------------------------------------------------
// Gather: warp per dst node. acc += w_e * h[src_e][lane*4..+3]; fused ReLU.
// h is L2-resident (51.2 MB < 126 MB L2) -> gather runs at LTS throughput.
// ---------------------------------------------------------------------------
__global__ void k_gather(float* __restrict__ out) {
    const int node = (blockIdx.x * blockDim.x + threadIdx.x) >> 5;
    if (node >= N_NODES) return;
    const int l = threadIdx.x & 31;

    const int beg = g_rowstart[node];
    const int end = g_rowstart[node + 1];

    const float4* h4 = reinterpret_cast<const float4*>(g_h);
    float4 acc = make_float4(0.f, 0.f, 0.f, 0.f);

    int e = beg;
    for (; e + 3 < end; e += 4) {
        const int   s0 = g_csr_src[e];
        const int   s1 = g_csr_src[e + 1];
        const int   s2 = g_csr_src[e + 2];
        const int   s3 = g_csr_src[e + 3];
        const float w0 = g_csr_w[e];
        const float w1 = g_csr_w[e + 1];
        const float w2 = g_csr_w[e + 2];
        const float w3 = g_csr_w[e + 3];
        const float4 h0 = h4[(size_t)s0 * 32 + l];
        const float4 h1 = h4[(size_t)s1 * 32 + l];
        const float4 h2 = h4[(size_t)s2 * 32 + l];
        const float4 h3 = h4[(size_t)s3 * 32 + l];
        acc.x = fmaf(w0, h0.x, acc.x); acc.y = fmaf(w0, h0.y, acc.y);
        acc.z = fmaf(w0, h0.z, acc.z); acc.w = fmaf(w0, h0.w, acc.w);
        acc.x = fmaf(w1, h1.x, acc.x); acc.y = fmaf(w1, h1.y, acc.y);
        acc.z = fmaf(w1, h1.z, acc.z); acc.w = fmaf(w1, h1.w, acc.w);
        acc.x = fmaf(w2, h2.x, acc.x); acc.y = fmaf(w2, h2.y, acc.y);
        acc.z = fmaf(w2, h2.z, acc.z); acc.w = fmaf(w2, h2.w, acc.w);
        acc.x = fmaf(w3, h3.x, acc.x); acc.y = fmaf(w3, h3.y, acc.y);
        acc.z = fmaf(w3, h3.z, acc.z); acc.w = fmaf(w3, h3.w, acc.w);
    }
    for (; e < end; e++) {
        const int   s0 = g_csr_src[e];
        const float w0 = g_csr_w[e];
        const float4 h0 = h4[(size_t)s0 * 32 + l];
        acc.x = fmaf(w0, h0.x, acc.x); acc.y = fmaf(w0, h0.y, acc.y);
        acc.z = fmaf(w0, h0.z, acc.z); acc.w = fmaf(w0, h0.w, acc.w);
    }

    acc.x = fmaxf(acc.x, 0.f);
    acc.y = fmaxf(acc.y, 0.f);
    acc.z = fmaxf(acc.z, 0.f);
    acc.w = fmaxf(acc.w, 0.f);

    reinterpret_cast<float4*>(out)[(size_t)node * 32 + l] = acc;
}

// ---------------------------------------------------------------------------
// Launch.  Inputs: x, W, b, edge_weight, edge_src, edge_dst
// ---------------------------------------------------------------------------
extern "C" void kernel_launch(void* const* d_in, const int* in_sizes, int n_in,
                              void* d_out, int out_size) {
    const float* x  = (const float*)d_in[0];
    const float* W  = (const float*)d_in[1];
    const float* b  = (const float*)d_in[2];
    const float* ew = (const float*)d_in[3];
    const int*   es = (const int*)  d_in[4];
    const int*   ed = (const int*)  d_in[5];
    float*       out = (float*)d_out;

    // Linear layer
    k_transpose_w<<<(D_IN * D_OUT + 255) / 256, 256>>>(W);
    k_gemm<<<N_NODES / 32, 256>>>(x, b);

    // CSR-by-dst build
    k_zero_deg<<<(N_NODES + 255) / 256, 256>>>();
    k_hist<<<(N_EDGES + 255) / 256, 256>>>(ed);
    k_scan1<<<N_SCAN_BLOCKS, SCAN_BLK>>>();
    k_scan2<<<1, 32>>>();
    k_scan3<<<(N_NODES + 255) / 256, 256>>>();
    k_fill<<<(N_EDGES + 255) / 256, 256>>>(es, ed, ew);

    // Gather + fused ReLU (writes every output exactly once)
    k_gather<<<(N_NODES * 32 + 255) / 256, 256>>>(out);
}